// round 6
// baseline (speedup 1.0000x reference)
#include <cuda_runtime.h>
#include <cuda_bf16.h>
#include <math.h>
#include <stdint.h>

#define NMAT 4
#define NSUB 4096
#define DIM 64
#define KTOP 20
#define NROWS 8192
#define DELTA 0.008f

// device global scratch (no allocation allowed)
__device__ float g_v1[NMAT][NSUB][DIM];
__device__ float g_v2[NMAT][NSUB][DIM];
__device__ __nv_bfloat16 g_v1b[NMAT][NSUB][DIM];
__device__ __nv_bfloat16 g_v2b[NMAT][NSUB][DIM];
__device__ float          g_cval[NROWS][64];
__device__ unsigned short g_ccol[NROWS][64];

__device__ __forceinline__ uint32_t smem_u32(const void* p) {
    uint32_t a;
    asm("{ .reg .u64 t; cvta.to.shared.u64 t, %1; cvt.u32.u64 %0, t; }" : "=r"(a) : "l"(p));
    return a;
}

// ---------------------------------------------------------------------------
// Zero the 256MB output
// ---------------------------------------------------------------------------
__global__ void zero_kernel(float4* out, int n4) {
    int stride = gridDim.x * blockDim.x;
    for (int t = blockIdx.x * blockDim.x + threadIdx.x; t < n4; t += stride)
        out[t] = make_float4(0.f, 0.f, 0.f, 0.f);
}

// ---------------------------------------------------------------------------
// v = emb @ w + b (fp32) + bf16 copy for the tensor path
// ---------------------------------------------------------------------------
__global__ void compute_v_kernel(const float* __restrict__ emb1,
                                 const float* __restrict__ emb2,
                                 const float* __restrict__ w1,
                                 const float* __restrict__ w2,
                                 const float* __restrict__ b1,
                                 const float* __restrict__ b2) {
    int which = blockIdx.z;
    int k = blockIdx.y;
    int tile = blockIdx.x;
    const float* emb = which ? emb2 : emb1;
    const float* w   = which ? w2   : w1;
    const float* b   = which ? b2   : b1;
    float* vout            = which ? &g_v2[0][0][0]  : &g_v1[0][0][0];
    __nv_bfloat16* voutb   = which ? &g_v2b[0][0][0] : &g_v1b[0][0][0];

    __shared__ float semb[64 * 65];
    __shared__ float sw[64 * 64];
    __shared__ float sb[64];

    int tid = threadIdx.x;
    for (int t = tid; t < 4096; t += 256) {
        int r = t >> 6, e = t & 63;
        semb[r * 65 + e] = emb[(size_t)(k * NSUB + tile * 64 + r) * 64 + e];
        sw[t] = w[k * 4096 + t];
    }
    if (tid < 64) sb[tid] = b[k * 64 + tid];
    __syncthreads();

    int nl = tid & 63, q = tid >> 6;
    float acc[16];
#pragma unroll
    for (int d = 0; d < 16; d++) acc[d] = 0.f;

#pragma unroll 4
    for (int e = 0; e < 64; e++) {
        float a = semb[nl * 65 + e];
#pragma unroll
        for (int jj = 0; jj < 4; jj++) {
            float4 wv = *(const float4*)&sw[e * 64 + q * 16 + jj * 4];
            acc[jj * 4 + 0] += a * wv.x;
            acc[jj * 4 + 1] += a * wv.y;
            acc[jj * 4 + 2] += a * wv.z;
            acc[jj * 4 + 3] += a * wv.w;
        }
    }

    size_t rowoff = (size_t)(k * NSUB + tile * 64 + nl) * 64;
    float* orow = vout + rowoff;
    __nv_bfloat16* orowb = voutb + rowoff;
#pragma unroll
    for (int dd = 0; dd < 16; dd++) {
        int d = q * 16 + dd;
        float v = acc[dd] + sb[d];
        orow[d]  = v;
        orowb[d] = __float2bfloat16(v);
    }
}

// ---------------------------------------------------------------------------
// HMMA (mma.sync bf16) scoring + streaming per-row top-32 (bf16-level).
// grid = (half: 2, row-tile: 64), 256 threads. CTA: 128 rows x 4096 cols,
// 64 chunks of 64 cols. Warp w = row band w*16..+15.
// smem (bytes): A[128][72]bf16 @0 (18432), B 2x[64][72]bf16 @18432 (9216 ea),
// scores[128][66]f32 @36864 (33792), lv[128][32]f32 @70656, lc[128][32]u16 @87040.
// Total 95232.
// ---------------------------------------------------------------------------
#define SPITCH 72      // bf16 elems per smem row (144B: 9 x 16B -> LDSM conflict-free)
#define OFF_A  0
#define OFF_B  18432
#define OFF_SC 36864
#define OFF_LV 70656
#define OFF_LC 87040
#define SM_TOTAL 95232

__global__ void __launch_bounds__(256, 1) score_mma_kernel() {
    extern __shared__ char smem[];
    uint32_t sbase = smem_u32(smem);
    int tid = threadIdx.x, wid = tid >> 5, lane = tid & 31;
    int half = blockIdx.x, rt = blockIdx.y;
    int k = (rt >> 5) * 2 + half;
    int nbase = (rt & 31) * 128;
    int rowg0 = rt * 128;

    // load A (128 rows x 128B) into pitched smem
    {
        const int4* src = (const int4*)&g_v1b[k][nbase][0];
        for (int f = tid; f < 1024; f += 256) {
            int r = f >> 3, q = f & 7;
            *(int4*)(smem + OFF_A + r * 144 + q * 16) = src[f];
        }
    }
    // load B chunk 0
    {
        const int4* src = (const int4*)&g_v2b[k][0][0];
        for (int f = tid; f < 512; f += 256) {
            int r = f >> 3, q = f & 7;
            *(int4*)(smem + OFF_B + r * 144 + q * 16) = src[f];
        }
    }
    // init lists
    float* lvg = (float*)(smem + OFF_LV);
    unsigned short* lcg = (unsigned short*)(smem + OFF_LC);
    for (int t = tid; t < 4096; t += 256) lvg[t] = -1e30f;
    __syncthreads();

    // preload A fragments: 4 k-steps x 4 regs
    uint32_t af[4][4];
    {
        uint32_t abase = sbase + OFF_A + (wid * 16 + (lane & 15)) * 144 + (lane >> 4) * 16;
#pragma unroll
        for (int ks = 0; ks < 4; ks++) {
            asm volatile("ldmatrix.sync.aligned.m8n8.x4.shared.b16 {%0,%1,%2,%3}, [%4];"
                         : "=r"(af[ks][0]), "=r"(af[ks][1]), "=r"(af[ks][2]), "=r"(af[ks][3])
                         : "r"(abase + ks * 32));
        }
    }

    float* sc = (float*)(smem + OFF_SC);
    int drow = wid * 16 + (lane >> 2);          // accumulator row (and +8)
    int dcol = (lane & 3) * 2;

    for (int cc = 0; cc < 64; cc++) {
        uint32_t bbuf = sbase + OFF_B + (cc & 1) * 9216;
        // lanes 0-7: rows n, k-lo; lanes 8-15: rows n, k-hi; 16-31 replicate
        uint32_t baddr0 = bbuf + (lane & 7) * 144 + ((lane >> 3) & 1) * 16;

        float acc[8][4];
#pragma unroll
        for (int nt = 0; nt < 8; nt++) {
#pragma unroll
            for (int s = 0; s < 4; s++) acc[nt][s] = 0.f;
        }

#pragma unroll
        for (int nt = 0; nt < 8; nt++) {
            uint32_t ba = baddr0 + nt * 8 * 144;
#pragma unroll
            for (int ks = 0; ks < 4; ks++) {
                uint32_t b0, b1;
                asm volatile("ldmatrix.sync.aligned.m8n8.x2.shared.b16 {%0,%1}, [%2];"
                             : "=r"(b0), "=r"(b1) : "r"(ba + ks * 32));
                asm volatile("mma.sync.aligned.m16n8k16.row.col.f32.bf16.bf16.f32 "
                             "{%0,%1,%2,%3}, {%4,%5,%6,%7}, {%8,%9}, {%0,%1,%2,%3};"
                             : "+f"(acc[nt][0]), "+f"(acc[nt][1]),
                               "+f"(acc[nt][2]), "+f"(acc[nt][3])
                             : "r"(af[ks][0]), "r"(af[ks][1]),
                               "r"(af[ks][2]), "r"(af[ks][3]), "r"(b0), "r"(b1));
            }
        }

        // stage scores: sc[row*66 + col]
#pragma unroll
        for (int nt = 0; nt < 8; nt++) {
            int c = nt * 8 + dcol;
            *(float2*)&sc[drow * 66 + c]       = make_float2(acc[nt][0], acc[nt][1]);
            *(float2*)&sc[(drow + 8) * 66 + c] = make_float2(acc[nt][2], acc[nt][3]);
        }
        __syncthreads();

        if (tid < 128) {
            // drain own row into sorted-ascending top-32
            int r = tid;
            float* lv = lvg + r * 32;
            unsigned short* lc = lcg + r * 32;
            float thr = lv[0];
            const float* row = &sc[r * 66];
            int colg = cc * 64;
            for (int c = 0; c < 64; c++) {
                float v = row[c];
                if (v > thr) {
                    int pos = 0;
                    while (pos < 31 && lv[pos + 1] < v) {
                        lv[pos] = lv[pos + 1]; lc[pos] = lc[pos + 1]; pos++;
                    }
                    lv[pos] = v; lc[pos] = (unsigned short)(colg + c);
                    thr = lv[0];
                }
            }
        } else if (cc + 1 < 64) {
            // load next B chunk into the other buffer
            const int4* src = (const int4*)&g_v2b[k][(cc + 1) * 64][0];
            char* dst = smem + OFF_B + ((cc + 1) & 1) * 9216;
            for (int f = tid - 128; f < 512; f += 128) {
                int r = f >> 3, q = f & 7;
                *(int4*)(dst + r * 144 + q * 16) = src[f];
            }
        }
        __syncthreads();
    }

    // writeback candidate lists
    if (tid < 128) {
        int r = tid;
        int rowg = rowg0 + r;
#pragma unroll 1
        for (int i = 0; i < 32; i++) {
            g_cval[rowg][half * 32 + i] = lvg[r * 32 + i];
            g_ccol[rowg][half * 32 + i] = lcg[r * 32 + i];
        }
    }
}

// ---------------------------------------------------------------------------
// Merge: warp/row. 64 bf16-level candidates -> bf16 20th (pass 1) ->
// fp32 rescore of candidates >= thr-DELTA -> exact top-20 (pass 2) -> scatter.
// ---------------------------------------------------------------------------
__global__ void merge_rescore_kernel(float* __restrict__ out) {
    __shared__ float sv1[8][2][64];
    int w = threadIdx.x >> 5, lane = threadIdx.x & 31;
    int row = blockIdx.x * 8 + w;
    int mod_i = row >> 12, rloc = row & 4095;

    for (int t = lane; t < 128; t += 32) {
        int h = t >> 6, d = t & 63;
        sv1[w][h][d] = g_v1[mod_i * 2 + h][rloc][d];
    }
    __syncwarp();

    float wv[2]; int col[2];
#pragma unroll
    for (int s = 0; s < 2; s++) {
        wv[s]  = g_cval[row][lane * 2 + s];
        col[s] = (int)g_ccol[row][lane * 2 + s];
    }
    int hh[2];
    hh[0] = (lane * 2 + 0) >> 5;   // which half-list this slot came from
    hh[1] = (lane * 2 + 1) >> 5;

    // pass 1: 20th-largest bf16-level value
    float a0 = wv[0], a1 = wv[1];
    float thr = 0.f;
#pragma unroll
    for (int kk = 0; kk < KTOP; kk++) {
        float bv = a0; int bs = 0;
        if (a1 > bv) { bv = a1; bs = 1; }
        int bi = lane * 2 + bs;
#pragma unroll
        for (int off = 16; off > 0; off >>= 1) {
            float ov = __shfl_xor_sync(0xffffffffu, bv, off);
            int   oi = __shfl_xor_sync(0xffffffffu, bi, off);
            if (ov > bv || (ov == bv && oi < bi)) { bv = ov; bi = oi; }
        }
        if (lane == (bi >> 1)) {
            if ((bi & 1) == 0) a0 = -1e30f; else a1 = -1e30f;
        }
        thr = bv;
    }

    // rescore survivors in exact fp32
    float rv[2]; int gc[2];
#pragma unroll
    for (int s = 0; s < 2; s++) {
        int h = hh[s];
        gc[s] = h * 4096 + col[s];
        if (wv[s] >= thr - DELTA) {
            const float4* v2c = (const float4*)&g_v2[mod_i * 2 + h][col[s]][0];
            const float4* v1c = (const float4*)&sv1[w][h][0];
            float acc = 0.f;
#pragma unroll
            for (int dd = 0; dd < 16; dd++) {
                float4 x = v1c[dd], y = v2c[dd];
                acc += x.x * y.x + x.y * y.y + x.z * y.z + x.w * y.w;
            }
            rv[s] = acc;
        } else {
            rv[s] = -1e30f;
        }
    }

    // pass 2: exact top-20 over rescored values, scatter tanh
#pragma unroll
    for (int kk = 0; kk < KTOP; kk++) {
        float bv = rv[0]; int bs = 0;
        if (rv[1] > bv) { bv = rv[1]; bs = 1; }
        int bc = gc[bs];
        int bi = lane * 2 + bs;
#pragma unroll
        for (int off = 16; off > 0; off >>= 1) {
            float ov = __shfl_xor_sync(0xffffffffu, bv, off);
            int   oc = __shfl_xor_sync(0xffffffffu, bc, off);
            int   oi = __shfl_xor_sync(0xffffffffu, bi, off);
            if (ov > bv || (ov == bv && oi < bi)) { bv = ov; bc = oc; bi = oi; }
        }
        if (lane == (bi >> 1)) {
            if ((bi & 1) == 0) rv[0] = -1e30f; else rv[1] = -1e30f;
        }
        if (lane == kk) {
            float t = (bv > 0.f) ? tanhf(3.0f * bv) : 0.f;
            out[(size_t)row * NROWS + bc] = t;
        }
    }
}

// ---------------------------------------------------------------------------
extern "C" void kernel_launch(void* const* d_in, const int* in_sizes, int n_in,
                              void* d_out, int out_size) {
    const float* emb1 = (const float*)d_in[1];
    const float* emb2 = (const float*)d_in[2];
    const float* w1   = (const float*)d_in[3];
    const float* w2   = (const float*)d_in[4];
    const float* b1   = (const float*)d_in[5];
    const float* b2   = (const float*)d_in[6];
    float* out = (float*)d_out;

    cudaFuncSetAttribute(score_mma_kernel,
                         cudaFuncAttributeMaxDynamicSharedMemorySize, SM_TOTAL);

    zero_kernel<<<8192, 256>>>((float4*)out, out_size / 4);
    compute_v_kernel<<<dim3(64, NMAT, 2), 256>>>(emb1, emb2, w1, w2, b1, b2);
    score_mma_kernel<<<dim3(2, 64), 256, SM_TOTAL>>>();
    merge_rescore_kernel<<<NROWS / 8, 256>>>(out);
}

// round 7
// speedup vs baseline: 4.4017x; 4.4017x over previous
#include <cuda_runtime.h>
#include <cuda_bf16.h>
#include <math.h>
#include <stdint.h>

#define NMAT 4
#define NSUB 4096
#define DIM 64
#define KTOP 20
#define NROWS 8192
#define DELTA 0.008f
#define FULLM 0xffffffffu

// device global scratch (no allocation allowed)
__device__ float g_v1[NMAT][NSUB][DIM];
__device__ float g_v2[NMAT][NSUB][DIM];
__device__ __nv_bfloat16 g_v1b[NMAT][NSUB][DIM];
__device__ __nv_bfloat16 g_v2b[NMAT][NSUB][DIM];
__device__ float          g_cval[NROWS][64];
__device__ unsigned short g_ccol[NROWS][64];

__device__ __forceinline__ uint32_t smem_u32(const void* p) {
    uint32_t a;
    asm("{ .reg .u64 t; cvta.to.shared.u64 t, %1; cvt.u32.u64 %0, t; }" : "=r"(a) : "l"(p));
    return a;
}

// ---------------------------------------------------------------------------
// Zero the 256MB output
// ---------------------------------------------------------------------------
__global__ void zero_kernel(float4* out, int n4) {
    int stride = gridDim.x * blockDim.x;
    for (int t = blockIdx.x * blockDim.x + threadIdx.x; t < n4; t += stride)
        out[t] = make_float4(0.f, 0.f, 0.f, 0.f);
}

// ---------------------------------------------------------------------------
// v = emb @ w + b (fp32) + bf16 copy for the tensor path
// ---------------------------------------------------------------------------
__global__ void compute_v_kernel(const float* __restrict__ emb1,
                                 const float* __restrict__ emb2,
                                 const float* __restrict__ w1,
                                 const float* __restrict__ w2,
                                 const float* __restrict__ b1,
                                 const float* __restrict__ b2) {
    int which = blockIdx.z;
    int k = blockIdx.y;
    int tile = blockIdx.x;
    const float* emb = which ? emb2 : emb1;
    const float* w   = which ? w2   : w1;
    const float* b   = which ? b2   : b1;
    float* vout            = which ? &g_v2[0][0][0]  : &g_v1[0][0][0];
    __nv_bfloat16* voutb   = which ? &g_v2b[0][0][0] : &g_v1b[0][0][0];

    __shared__ float semb[64 * 65];
    __shared__ float sw[64 * 64];
    __shared__ float sb[64];

    int tid = threadIdx.x;
    for (int t = tid; t < 4096; t += 256) {
        int r = t >> 6, e = t & 63;
        semb[r * 65 + e] = emb[(size_t)(k * NSUB + tile * 64 + r) * 64 + e];
        sw[t] = w[k * 4096 + t];
    }
    if (tid < 64) sb[tid] = b[k * 64 + tid];
    __syncthreads();

    int nl = tid & 63, q = tid >> 6;
    float acc[16];
#pragma unroll
    for (int d = 0; d < 16; d++) acc[d] = 0.f;

#pragma unroll 4
    for (int e = 0; e < 64; e++) {
        float a = semb[nl * 65 + e];
#pragma unroll
        for (int jj = 0; jj < 4; jj++) {
            float4 wv = *(const float4*)&sw[e * 64 + q * 16 + jj * 4];
            acc[jj * 4 + 0] += a * wv.x;
            acc[jj * 4 + 1] += a * wv.y;
            acc[jj * 4 + 2] += a * wv.z;
            acc[jj * 4 + 3] += a * wv.w;
        }
    }

    size_t rowoff = (size_t)(k * NSUB + tile * 64 + nl) * 64;
    float* orow = vout + rowoff;
    __nv_bfloat16* orowb = voutb + rowoff;
#pragma unroll
    for (int dd = 0; dd < 16; dd++) {
        int d = q * 16 + dd;
        float v = acc[dd] + sb[d];
        orow[d]  = v;
        orowb[d] = __float2bfloat16(v);
    }
}

// ---------------------------------------------------------------------------
// HMMA scoring + warp-cooperative register-resident per-row top-32.
// grid = (half: 2, row-tile: 64), 256 threads. CTA: 128 rows x 4096 cols,
// 64 chunks of 64 cols. Warp w owns rows w*16..w*16+15; lane l holds slot l
// of each row's 32-deep ascending sorted candidate list (registers).
// smem: A[128][72]bf16 @0, B 2x[64][72]bf16 @18432, scores[128][66]f32 @36864.
// ---------------------------------------------------------------------------
#define OFF_A  0
#define OFF_B  18432
#define OFF_SC 36864
#define SM_TOTAL 70656

__global__ void __launch_bounds__(256, 1) score_mma_kernel() {
    extern __shared__ char smem[];
    uint32_t sbase = smem_u32(smem);
    int tid = threadIdx.x, wid = tid >> 5, lane = tid & 31;
    int half = blockIdx.x, rt = blockIdx.y;
    int k = (rt >> 5) * 2 + half;
    int nbase = (rt & 31) * 128;
    int rowg0 = rt * 128;

    // load A (128 rows x 128B) into pitched smem
    {
        const int4* src = (const int4*)&g_v1b[k][nbase][0];
        for (int f = tid; f < 1024; f += 256) {
            int r = f >> 3, q = f & 7;
            *(int4*)(smem + OFF_A + r * 144 + q * 16) = src[f];
        }
    }
    // load B chunk 0 into buffer 0
    {
        const int4* src = (const int4*)&g_v2b[k][0][0];
        for (int f = tid; f < 512; f += 256) {
            int r = f >> 3, q = f & 7;
            *(int4*)(smem + OFF_B + r * 144 + q * 16) = src[f];
        }
    }
    __syncthreads();

    // preload A fragments: 4 k-steps x 4 regs
    uint32_t af[4][4];
    {
        uint32_t abase = sbase + OFF_A + (wid * 16 + (lane & 15)) * 144 + (lane >> 4) * 16;
#pragma unroll
        for (int ks = 0; ks < 4; ks++) {
            asm volatile("ldmatrix.sync.aligned.m8n8.x4.shared.b16 {%0,%1,%2,%3}, [%4];"
                         : "=r"(af[ks][0]), "=r"(af[ks][1]), "=r"(af[ks][2]), "=r"(af[ks][3])
                         : "r"(abase + ks * 32));
        }
    }

    // register-resident sorted lists: lane l = slot l (ascending), 16 rows/warp
    float Lv[16]; int Lc[16];
#pragma unroll
    for (int rr = 0; rr < 16; rr++) { Lv[rr] = -1e30f; Lc[rr] = 0; }

    float* sc = (float*)(smem + OFF_SC);
    int drow = wid * 16 + (lane >> 2);
    int dcol = (lane & 3) * 2;

    for (int cc = 0; cc < 64; cc++) {
        uint32_t bbuf = sbase + OFF_B + (cc & 1) * 9216;
        uint32_t baddr0 = bbuf + (lane & 7) * 144 + ((lane >> 3) & 1) * 16;

        float acc[8][4];
#pragma unroll
        for (int nt = 0; nt < 8; nt++)
#pragma unroll
            for (int s = 0; s < 4; s++) acc[nt][s] = 0.f;

#pragma unroll
        for (int nt = 0; nt < 8; nt++) {
            uint32_t ba = baddr0 + nt * 8 * 144;
#pragma unroll
            for (int ks = 0; ks < 4; ks++) {
                uint32_t b0, b1;
                asm volatile("ldmatrix.sync.aligned.m8n8.x2.shared.b16 {%0,%1}, [%2];"
                             : "=r"(b0), "=r"(b1) : "r"(ba + ks * 32));
                asm volatile("mma.sync.aligned.m16n8k16.row.col.f32.bf16.bf16.f32 "
                             "{%0,%1,%2,%3}, {%4,%5,%6,%7}, {%8,%9}, {%0,%1,%2,%3};"
                             : "+f"(acc[nt][0]), "+f"(acc[nt][1]),
                               "+f"(acc[nt][2]), "+f"(acc[nt][3])
                             : "r"(af[ks][0]), "r"(af[ks][1]),
                               "r"(af[ks][2]), "r"(af[ks][3]), "r"(b0), "r"(b1));
            }
        }

        // stage scores: sc[row*66 + col]
#pragma unroll
        for (int nt = 0; nt < 8; nt++) {
            int c = nt * 8 + dcol;
            *(float2*)&sc[drow * 66 + c]       = make_float2(acc[nt][0], acc[nt][1]);
            *(float2*)&sc[(drow + 8) * 66 + c] = make_float2(acc[nt][2], acc[nt][3]);
        }
        __syncthreads();

        // prefetch next B chunk (all threads; other buffer)
        if (cc + 1 < 64) {
            const int4* src = (const int4*)&g_v2b[k][(cc + 1) * 64][0];
            char* dst = smem + OFF_B + ((cc + 1) & 1) * 9216;
            for (int f = tid; f < 512; f += 256) {
                int r = f >> 3, q = f & 7;
                *(int4*)(dst + r * 144 + q * 16) = src[f];
            }
        }

        // warp-cooperative selection over this warp's 16 rows
        int colg = cc * 64;
#pragma unroll
        for (int rr = 0; rr < 16; rr++) {
            int r = wid * 16 + rr;
            float thr = __shfl_sync(FULLM, Lv[rr], 0);
#pragma unroll
            for (int b = 0; b < 2; b++) {
                float val = sc[r * 66 + b * 32 + lane];
                unsigned m = __ballot_sync(FULLM, val > thr);
                while (m) {
                    int src = __ffs(m) - 1; m &= m - 1;
                    float v = __shfl_sync(FULLM, val, src);
                    if (v > thr) {   // uniform
                        int c = colg + b * 32 + src;
                        float nv = __shfl_down_sync(FULLM, Lv[rr], 1);
                        int   nc = __shfl_down_sync(FULLM, Lc[rr], 1);
                        bool pred  = Lv[rr] < v;
                        bool npred = (lane < 31) && (nv < v);
                        Lv[rr] = pred ? (npred ? nv : v) : Lv[rr];
                        Lc[rr] = pred ? (npred ? nc : c) : Lc[rr];
                        thr = __shfl_sync(FULLM, Lv[rr], 0);
                    }
                }
            }
        }
        __syncthreads();
    }

    // writeback candidate lists (lane l = slot l)
#pragma unroll
    for (int rr = 0; rr < 16; rr++) {
        int rowg = rowg0 + wid * 16 + rr;
        g_cval[rowg][half * 32 + lane] = Lv[rr];
        g_ccol[rowg][half * 32 + lane] = (unsigned short)Lc[rr];
    }
}

// ---------------------------------------------------------------------------
// Merge: warp/row. 64 bf16-level candidates -> bf16 20th (pass 1) ->
// fp32 rescore of candidates >= thr-DELTA -> exact top-20 (pass 2) -> scatter.
// ---------------------------------------------------------------------------
__global__ void merge_rescore_kernel(float* __restrict__ out) {
    __shared__ float sv1[8][2][64];
    int w = threadIdx.x >> 5, lane = threadIdx.x & 31;
    int row = blockIdx.x * 8 + w;
    int mod_i = row >> 12, rloc = row & 4095;

    for (int t = lane; t < 128; t += 32) {
        int h = t >> 6, d = t & 63;
        sv1[w][h][d] = g_v1[mod_i * 2 + h][rloc][d];
    }
    __syncwarp();

    float wv[2]; int col[2];
#pragma unroll
    for (int s = 0; s < 2; s++) {
        wv[s]  = g_cval[row][lane * 2 + s];
        col[s] = (int)g_ccol[row][lane * 2 + s];
    }
    int hh[2];
    hh[0] = (lane * 2 + 0) >> 5;
    hh[1] = (lane * 2 + 1) >> 5;

    // pass 1: 20th-largest bf16-level value
    float a0 = wv[0], a1 = wv[1];
    float thr = 0.f;
#pragma unroll
    for (int kk = 0; kk < KTOP; kk++) {
        float bv = a0; int bs = 0;
        if (a1 > bv) { bv = a1; bs = 1; }
        int bi = lane * 2 + bs;
#pragma unroll
        for (int off = 16; off > 0; off >>= 1) {
            float ov = __shfl_xor_sync(FULLM, bv, off);
            int   oi = __shfl_xor_sync(FULLM, bi, off);
            if (ov > bv || (ov == bv && oi < bi)) { bv = ov; bi = oi; }
        }
        if (lane == (bi >> 1)) {
            if ((bi & 1) == 0) a0 = -1e30f; else a1 = -1e30f;
        }
        thr = bv;
    }

    // rescore survivors in exact fp32
    float rv[2]; int gc[2];
#pragma unroll
    for (int s = 0; s < 2; s++) {
        int h = hh[s];
        gc[s] = h * 4096 + col[s];
        if (wv[s] >= thr - DELTA) {
            const float4* v2c = (const float4*)&g_v2[mod_i * 2 + h][col[s]][0];
            const float4* v1c = (const float4*)&sv1[w][h][0];
            float acc = 0.f;
#pragma unroll
            for (int dd = 0; dd < 16; dd++) {
                float4 x = v1c[dd], y = v2c[dd];
                acc += x.x * y.x + x.y * y.y + x.z * y.z + x.w * y.w;
            }
            rv[s] = acc;
        } else {
            rv[s] = -1e30f;
        }
    }

    // pass 2: exact top-20 over rescored values, scatter tanh
#pragma unroll
    for (int kk = 0; kk < KTOP; kk++) {
        float bv = rv[0]; int bs = 0;
        if (rv[1] > bv) { bv = rv[1]; bs = 1; }
        int bc = gc[bs];
        int bi = lane * 2 + bs;
#pragma unroll
        for (int off = 16; off > 0; off >>= 1) {
            float ov = __shfl_xor_sync(FULLM, bv, off);
            int   oc = __shfl_xor_sync(FULLM, bc, off);
            int   oi = __shfl_xor_sync(FULLM, bi, off);
            if (ov > bv || (ov == bv && oi < bi)) { bv = ov; bc = oc; bi = oi; }
        }
        if (lane == (bi >> 1)) {
            if ((bi & 1) == 0) rv[0] = -1e30f; else rv[1] = -1e30f;
        }
        if (lane == kk) {
            float t = (bv > 0.f) ? tanhf(3.0f * bv) : 0.f;
            out[(size_t)row * NROWS + bc] = t;
        }
    }
}

// ---------------------------------------------------------------------------
extern "C" void kernel_launch(void* const* d_in, const int* in_sizes, int n_in,
                              void* d_out, int out_size) {
    const float* emb1 = (const float*)d_in[1];
    const float* emb2 = (const float*)d_in[2];
    const float* w1   = (const float*)d_in[3];
    const float* w2   = (const float*)d_in[4];
    const float* b1   = (const float*)d_in[5];
    const float* b2   = (const float*)d_in[6];
    float* out = (float*)d_out;

    cudaFuncSetAttribute(score_mma_kernel,
                         cudaFuncAttributeMaxDynamicSharedMemorySize, SM_TOTAL);

    zero_kernel<<<8192, 256>>>((float4*)out, out_size / 4);
    compute_v_kernel<<<dim3(64, NMAT, 2), 256>>>(emb1, emb2, w1, w2, b1, b2);
    score_mma_kernel<<<dim3(2, 64), 256, SM_TOTAL>>>();
    merge_rescore_kernel<<<NROWS / 8, 256>>>(out);
}

// round 8
// speedup vs baseline: 7.5984x; 1.7262x over previous
#include <cuda_runtime.h>
#include <cuda_bf16.h>
#include <math.h>
#include <stdint.h>

#define NMAT 4
#define NSUB 4096
#define DIM 64
#define KTOP 20
#define NROWS 8192
#define DELTA 0.008f
#define FULLM 0xffffffffu
#define CAND 48            // candidates per half-row

// device global scratch (no allocation allowed)
__device__ float g_v1[NMAT][NSUB][DIM];
__device__ float g_v2[NMAT][NSUB][DIM];
__device__ __nv_bfloat16 g_v1b[NMAT][NSUB][DIM];
__device__ __nv_bfloat16 g_v2b[NMAT][NSUB][DIM];
__device__ float          g_cm[NROWS][128];       // per-row chunk maxima
__device__ float          g_T[NROWS];             // per-row filter threshold
__device__ float          g_cval[NROWS][2 * CAND];
__device__ unsigned short g_ccol[NROWS][2 * CAND];

__device__ __forceinline__ uint32_t smem_u32(const void* p) {
    uint32_t a;
    asm("{ .reg .u64 t; cvta.to.shared.u64 t, %1; cvt.u32.u64 %0, t; }" : "=r"(a) : "l"(p));
    return a;
}

// ---------------------------------------------------------------------------
// Zero the 256MB output
// ---------------------------------------------------------------------------
__global__ void zero_kernel(float4* out, int n4) {
    int stride = gridDim.x * blockDim.x;
    for (int t = blockIdx.x * blockDim.x + threadIdx.x; t < n4; t += stride)
        out[t] = make_float4(0.f, 0.f, 0.f, 0.f);
}

// ---------------------------------------------------------------------------
// v = emb @ w + b (fp32) + bf16 copy
// ---------------------------------------------------------------------------
__global__ void compute_v_kernel(const float* __restrict__ emb1,
                                 const float* __restrict__ emb2,
                                 const float* __restrict__ w1,
                                 const float* __restrict__ w2,
                                 const float* __restrict__ b1,
                                 const float* __restrict__ b2) {
    int which = blockIdx.z;
    int k = blockIdx.y;
    int tile = blockIdx.x;
    const float* emb = which ? emb2 : emb1;
    const float* w   = which ? w2   : w1;
    const float* b   = which ? b2   : b1;
    float* vout            = which ? &g_v2[0][0][0]  : &g_v1[0][0][0];
    __nv_bfloat16* voutb   = which ? &g_v2b[0][0][0] : &g_v1b[0][0][0];

    __shared__ float semb[64 * 65];
    __shared__ float sw[64 * 64];
    __shared__ float sb[64];

    int tid = threadIdx.x;
    for (int t = tid; t < 4096; t += 256) {
        int r = t >> 6, e = t & 63;
        semb[r * 65 + e] = emb[(size_t)(k * NSUB + tile * 64 + r) * 64 + e];
        sw[t] = w[k * 4096 + t];
    }
    if (tid < 64) sb[tid] = b[k * 64 + tid];
    __syncthreads();

    int nl = tid & 63, q = tid >> 6;
    float acc[16];
#pragma unroll
    for (int d = 0; d < 16; d++) acc[d] = 0.f;

#pragma unroll 4
    for (int e = 0; e < 64; e++) {
        float a = semb[nl * 65 + e];
#pragma unroll
        for (int jj = 0; jj < 4; jj++) {
            float4 wv = *(const float4*)&sw[e * 64 + q * 16 + jj * 4];
            acc[jj * 4 + 0] += a * wv.x;
            acc[jj * 4 + 1] += a * wv.y;
            acc[jj * 4 + 2] += a * wv.z;
            acc[jj * 4 + 3] += a * wv.w;
        }
    }

    size_t rowoff = (size_t)(k * NSUB + tile * 64 + nl) * 64;
    float* orow = vout + rowoff;
    __nv_bfloat16* orowb = voutb + rowoff;
#pragma unroll
    for (int dd = 0; dd < 16; dd++) {
        int d = q * 16 + dd;
        float v = acc[dd] + sb[d];
        orow[d]  = v;
        orowb[d] = __float2bfloat16(v);
    }
}

// ---------------------------------------------------------------------------
// Shared HMMA plumbing (proven in R7): A pitched 144B rows, ldmatrix + mma.
// ---------------------------------------------------------------------------
#define OFF_A  0
#define OFF_B  18432
#define SM_AB  36864            // A + 2 B buffers

// compute one chunk's 32 accumulators from preloaded af and B buffer
#define MMA_CHUNK(acc, af, bbuf, lane)                                          \
    do {                                                                        \
        uint32_t baddr0 = (bbuf) + ((lane) & 7) * 144 + (((lane) >> 3) & 1) * 16; \
        _Pragma("unroll")                                                       \
        for (int nt = 0; nt < 8; nt++) {                                        \
            uint32_t ba = baddr0 + nt * 8 * 144;                                \
            _Pragma("unroll")                                                   \
            for (int ks = 0; ks < 4; ks++) {                                    \
                uint32_t b0, b1;                                                \
                asm volatile("ldmatrix.sync.aligned.m8n8.x2.shared.b16 {%0,%1}, [%2];" \
                             : "=r"(b0), "=r"(b1) : "r"(ba + ks * 32));         \
                asm volatile("mma.sync.aligned.m16n8k16.row.col.f32.bf16.bf16.f32 " \
                             "{%0,%1,%2,%3}, {%4,%5,%6,%7}, {%8,%9}, {%0,%1,%2,%3};" \
                             : "+f"(acc[nt][0]), "+f"(acc[nt][1]),              \
                               "+f"(acc[nt][2]), "+f"(acc[nt][3])               \
                             : "r"(af[ks][0]), "r"(af[ks][1]),                  \
                               "r"(af[ks][2]), "r"(af[ks][3]), "r"(b0), "r"(b1)); \
            }                                                                   \
        }                                                                       \
    } while (0)

__device__ __forceinline__ void load_A_and_B0(char* smem, int tid, int k, int nbase) {
    const int4* asrc = (const int4*)&g_v1b[k][nbase][0];
    for (int f = tid; f < 1024; f += 256) {
        int r = f >> 3, q = f & 7;
        *(int4*)(smem + OFF_A + r * 144 + q * 16) = asrc[f];
    }
    const int4* bsrc = (const int4*)&g_v2b[k][0][0];
    for (int f = tid; f < 512; f += 256) {
        int r = f >> 3, q = f & 7;
        *(int4*)(smem + OFF_B + r * 144 + q * 16) = bsrc[f];
    }
}

__device__ __forceinline__ void preload_af(uint32_t af[4][4], uint32_t sbase, int wid, int lane) {
    uint32_t abase = sbase + OFF_A + (wid * 16 + (lane & 15)) * 144 + (lane >> 4) * 16;
#pragma unroll
    for (int ks = 0; ks < 4; ks++) {
        asm volatile("ldmatrix.sync.aligned.m8n8.x4.shared.b16 {%0,%1,%2,%3}, [%4];"
                     : "=r"(af[ks][0]), "=r"(af[ks][1]), "=r"(af[ks][2]), "=r"(af[ks][3])
                     : "r"(abase + ks * 32));
    }
}

__device__ __forceinline__ void prefetch_B(char* smem, int tid, int k, int cc1) {
    const int4* src = (const int4*)&g_v2b[k][cc1 * 64][0];
    char* dst = smem + OFF_B + (cc1 & 1) * 9216;
    for (int f = tid; f < 512; f += 256) {
        int r = f >> 3, q = f & 7;
        *(int4*)(dst + r * 144 + q * 16) = src[f];
    }
}

// ---------------------------------------------------------------------------
// Pass 1: HMMA + per-row chunk maxima. grid (half:2, rowtile:64), 256 thr.
// ---------------------------------------------------------------------------
__global__ void __launch_bounds__(256, 1) score1_kernel() {
    extern __shared__ char smem[];
    uint32_t sbase = smem_u32(smem);
    int tid = threadIdx.x, wid = tid >> 5, lane = tid & 31;
    int half = blockIdx.x, rt = blockIdx.y;
    int k = (rt >> 5) * 2 + half;
    int nbase = (rt & 31) * 128;
    int rowg0 = rt * 128;

    load_A_and_B0(smem, tid, k, nbase);
    __syncthreads();

    uint32_t af[4][4];
    preload_af(af, sbase, wid, lane);

    int drow = wid * 16 + (lane >> 2);

    for (int cc = 0; cc < 64; cc++) {
        if (cc + 1 < 64) prefetch_B(smem, tid, k, cc + 1);

        uint32_t bbuf = sbase + OFF_B + (cc & 1) * 9216;
        float acc[8][4];
#pragma unroll
        for (int nt = 0; nt < 8; nt++)
#pragma unroll
            for (int s = 0; s < 4; s++) acc[nt][s] = 0.f;
        MMA_CHUNK(acc, af, bbuf, lane);

        // per-lane maxima for its two rows
        float mlo = acc[0][0], mhi = acc[0][2];
#pragma unroll
        for (int nt = 0; nt < 8; nt++) {
            mlo = fmaxf(mlo, fmaxf(acc[nt][0], acc[nt][1]));
            mhi = fmaxf(mhi, fmaxf(acc[nt][2], acc[nt][3]));
        }
        // quad reduce (lanes 4q..4q+3 share a row)
        mlo = fmaxf(mlo, __shfl_xor_sync(FULLM, mlo, 1));
        mlo = fmaxf(mlo, __shfl_xor_sync(FULLM, mlo, 2));
        mhi = fmaxf(mhi, __shfl_xor_sync(FULLM, mhi, 1));
        mhi = fmaxf(mhi, __shfl_xor_sync(FULLM, mhi, 2));
        if ((lane & 3) == 0) {
            g_cm[rowg0 + drow][half * 64 + cc]     = mlo;
            g_cm[rowg0 + drow + 8][half * 64 + cc] = mhi;
        }
        __syncthreads();
    }
}

// ---------------------------------------------------------------------------
// Threshold: T[row] = (20th largest of 128 chunk maxima) - DELTA. warp/row.
// ---------------------------------------------------------------------------
__global__ void thr_kernel() {
    int w = threadIdx.x >> 5, lane = threadIdx.x & 31;
    int row = blockIdx.x * 8 + w;

    float a[4];
#pragma unroll
    for (int s = 0; s < 4; s++) a[s] = g_cm[row][lane + 32 * s];

    float last = -1e30f;
#pragma unroll
    for (int kk = 0; kk < KTOP; kk++) {
        float bv = a[0]; int bs = 0;
        if (a[1] > bv) { bv = a[1]; bs = 1; }
        if (a[2] > bv) { bv = a[2]; bs = 2; }
        if (a[3] > bv) { bv = a[3]; bs = 3; }
        int bi = lane * 4 + bs;
#pragma unroll
        for (int off = 16; off > 0; off >>= 1) {
            float ov = __shfl_xor_sync(FULLM, bv, off);
            int   oi = __shfl_xor_sync(FULLM, bi, off);
            if (ov > bv || (ov == bv && oi < bi)) { bv = ov; bi = oi; }
        }
        if (lane == (bi >> 2)) {
            int ws = bi & 3;
            if      (ws == 0) a[0] = -1e30f;
            else if (ws == 1) a[1] = -1e30f;
            else if (ws == 2) a[2] = -1e30f;
            else              a[3] = -1e30f;
        }
        last = bv;
    }
    if (lane == 0) g_T[row] = last - DELTA;
}

// ---------------------------------------------------------------------------
// Pass 2: HMMA + filter-append values > T into per-row FIFOs.
// smem: A+B (36864) + fifov 128*48*4 @36864 + fifoc u16 @61440 + cnt @73728.
// ---------------------------------------------------------------------------
#define OFF_FV 36864
#define OFF_FC 61440
#define OFF_CN 73728
#define SM2_TOTAL 74240

__global__ void __launch_bounds__(256, 1) score2_kernel() {
    extern __shared__ char smem[];
    uint32_t sbase = smem_u32(smem);
    int tid = threadIdx.x, wid = tid >> 5, lane = tid & 31;
    int half = blockIdx.x, rt = blockIdx.y;
    int k = (rt >> 5) * 2 + half;
    int nbase = (rt & 31) * 128;
    int rowg0 = rt * 128;

    float* fv = (float*)(smem + OFF_FV);
    unsigned short* fc = (unsigned short*)(smem + OFF_FC);
    int* cnt = (int*)(smem + OFF_CN);
    if (tid < 128) cnt[tid] = 0;

    load_A_and_B0(smem, tid, k, nbase);
    __syncthreads();

    uint32_t af[4][4];
    preload_af(af, sbase, wid, lane);

    int drow = wid * 16 + (lane >> 2);
    int dcol = (lane & 3) * 2;
    float Tlo = g_T[rowg0 + drow];
    float Thi = g_T[rowg0 + drow + 8];
    unsigned short cbase = (unsigned short)(half * 4096);

    for (int cc = 0; cc < 64; cc++) {
        if (cc + 1 < 64) prefetch_B(smem, tid, k, cc + 1);

        uint32_t bbuf = sbase + OFF_B + (cc & 1) * 9216;
        float acc[8][4];
#pragma unroll
        for (int nt = 0; nt < 8; nt++)
#pragma unroll
            for (int s = 0; s < 4; s++) acc[nt][s] = 0.f;
        MMA_CHUNK(acc, af, bbuf, lane);

        // filter-append (rarely taken branches)
#pragma unroll
        for (int nt = 0; nt < 8; nt++) {
            int colb = cc * 64 + nt * 8 + dcol;
            if (acc[nt][0] > Tlo) {
                int p = atomicAdd(&cnt[drow], 1);
                if (p < CAND) { fv[drow * CAND + p] = acc[nt][0];
                                fc[drow * CAND + p] = (unsigned short)(cbase + colb); }
            }
            if (acc[nt][1] > Tlo) {
                int p = atomicAdd(&cnt[drow], 1);
                if (p < CAND) { fv[drow * CAND + p] = acc[nt][1];
                                fc[drow * CAND + p] = (unsigned short)(cbase + colb + 1); }
            }
            if (acc[nt][2] > Thi) {
                int p = atomicAdd(&cnt[drow + 8], 1);
                if (p < CAND) { fv[(drow + 8) * CAND + p] = acc[nt][2];
                                fc[(drow + 8) * CAND + p] = (unsigned short)(cbase + colb); }
            }
            if (acc[nt][3] > Thi) {
                int p = atomicAdd(&cnt[drow + 8], 1);
                if (p < CAND) { fv[(drow + 8) * CAND + p] = acc[nt][3];
                                fc[(drow + 8) * CAND + p] = (unsigned short)(cbase + colb + 1); }
            }
        }
        __syncthreads();
    }

    // writeback: half h owns slots [h*CAND, h*CAND+CAND)
    for (int t = tid; t < 128 * CAND; t += 256) {
        int r = t / CAND, i = t % CAND;
        int n = min(cnt[r], CAND);
        g_cval[rowg0 + r][half * CAND + i] = (i < n) ? fv[t] : -1e30f;
        g_ccol[rowg0 + r][half * CAND + i] = fc[t];
    }
}

// ---------------------------------------------------------------------------
// Merge: warp/row. Rescore all <=96 candidates in exact fp32, top-20, scatter.
// ---------------------------------------------------------------------------
__global__ void merge_rescore_kernel(float* __restrict__ out) {
    __shared__ float sv1[8][2][64];
    int w = threadIdx.x >> 5, lane = threadIdx.x & 31;
    int row = blockIdx.x * 8 + w;
    int mod_i = row >> 12, rloc = row & 4095;

    for (int t = lane; t < 128; t += 32) {
        int h = t >> 6, d = t & 63;
        sv1[w][h][d] = g_v1[mod_i * 2 + h][rloc][d];
    }
    __syncwarp();

    float rv[3]; int gc[3];
#pragma unroll
    for (int s = 0; s < 3; s++) {
        int idx = lane * 3 + s;
        float bval = g_cval[row][idx];
        int   col  = (int)g_ccol[row][idx];
        gc[s] = col;
        if (bval > -1e29f) {
            int h = col >> 12, cl = col & 4095;
            const float4* v2c = (const float4*)&g_v2[mod_i * 2 + h][cl][0];
            const float4* v1c = (const float4*)&sv1[w][h][0];
            float acc = 0.f;
#pragma unroll
            for (int dd = 0; dd < 16; dd++) {
                float4 x = v1c[dd], y = v2c[dd];
                acc += x.x * y.x + x.y * y.y + x.z * y.z + x.w * y.w;
            }
            rv[s] = acc;
        } else {
            rv[s] = -1e30f;
        }
    }

#pragma unroll
    for (int kk = 0; kk < KTOP; kk++) {
        float bv = rv[0]; int bs = 0;
        if (rv[1] > bv) { bv = rv[1]; bs = 1; }
        if (rv[2] > bv) { bv = rv[2]; bs = 2; }
        int bc = gc[bs];
        int bi = lane * 4 + bs;
#pragma unroll
        for (int off = 16; off > 0; off >>= 1) {
            float ov = __shfl_xor_sync(FULLM, bv, off);
            int   oc = __shfl_xor_sync(FULLM, bc, off);
            int   oi = __shfl_xor_sync(FULLM, bi, off);
            if (ov > bv || (ov == bv && oi < bi)) { bv = ov; bc = oc; bi = oi; }
        }
        if (lane == (bi >> 2)) rv[bi & 3] = -1e30f;
        if (lane == kk) {
            float t = (bv > 0.f) ? tanhf(3.0f * bv) : 0.f;
            out[(size_t)row * NROWS + bc] = t;
        }
    }
}

// ---------------------------------------------------------------------------
extern "C" void kernel_launch(void* const* d_in, const int* in_sizes, int n_in,
                              void* d_out, int out_size) {
    const float* emb1 = (const float*)d_in[1];
    const float* emb2 = (const float*)d_in[2];
    const float* w1   = (const float*)d_in[3];
    const float* w2   = (const float*)d_in[4];
    const float* b1   = (const float*)d_in[5];
    const float* b2   = (const float*)d_in[6];
    float* out = (float*)d_out;

    cudaFuncSetAttribute(score1_kernel,
                         cudaFuncAttributeMaxDynamicSharedMemorySize, SM_AB);
    cudaFuncSetAttribute(score2_kernel,
                         cudaFuncAttributeMaxDynamicSharedMemorySize, SM2_TOTAL);

    zero_kernel<<<8192, 256>>>((float4*)out, out_size / 4);
    compute_v_kernel<<<dim3(64, NMAT, 2), 256>>>(emb1, emb2, w1, w2, b1, b2);
    score1_kernel<<<dim3(2, 64), 256, SM_AB>>>();
    thr_kernel<<<NROWS / 8, 256>>>();
    score2_kernel<<<dim3(2, 64), 256, SM2_TOTAL>>>();
    merge_rescore_kernel<<<NROWS / 8, 256>>>(out);
}

// round 9
// speedup vs baseline: 9.5547x; 1.2575x over previous
#include <cuda_runtime.h>
#include <cuda_bf16.h>
#include <math.h>
#include <stdint.h>

#define NMAT 4
#define NSUB 4096
#define DIM 64
#define KTOP 20
#define NROWS 8192
#define DELTA 0.008f
#define FULLM 0xffffffffu
#define CAND 48            // candidates per half-row

// device global scratch (no allocation allowed)
__device__ float g_v1[NMAT][NSUB][DIM];
__device__ float g_v2[NMAT][NSUB][DIM];
__device__ __nv_bfloat16 g_v1b[NMAT][NSUB][DIM];
__device__ __nv_bfloat16 g_v2b[NMAT][NSUB][DIM];
__device__ float          g_cm[NROWS][256];       // per-row 32-col sub-chunk maxima
__device__ float          g_T[NROWS];             // per-row filter threshold
__device__ float          g_cval[NROWS][2 * CAND];
__device__ unsigned short g_ccol[NROWS][2 * CAND];

__device__ __forceinline__ uint32_t smem_u32(const void* p) {
    uint32_t a;
    asm("{ .reg .u64 t; cvta.to.shared.u64 t, %1; cvt.u32.u64 %0, t; }" : "=r"(a) : "l"(p));
    return a;
}

// ---------------------------------------------------------------------------
// v = emb @ w + b (fp32) + bf16 copy
// ---------------------------------------------------------------------------
__global__ void compute_v_kernel(const float* __restrict__ emb1,
                                 const float* __restrict__ emb2,
                                 const float* __restrict__ w1,
                                 const float* __restrict__ w2,
                                 const float* __restrict__ b1,
                                 const float* __restrict__ b2) {
    int which = blockIdx.z;
    int k = blockIdx.y;
    int tile = blockIdx.x;
    const float* emb = which ? emb2 : emb1;
    const float* w   = which ? w2   : w1;
    const float* b   = which ? b2   : b1;
    float* vout            = which ? &g_v2[0][0][0]  : &g_v1[0][0][0];
    __nv_bfloat16* voutb   = which ? &g_v2b[0][0][0] : &g_v1b[0][0][0];

    __shared__ float semb[64 * 65];
    __shared__ float sw[64 * 64];
    __shared__ float sb[64];

    int tid = threadIdx.x;
    for (int t = tid; t < 4096; t += 256) {
        int r = t >> 6, e = t & 63;
        semb[r * 65 + e] = emb[(size_t)(k * NSUB + tile * 64 + r) * 64 + e];
        sw[t] = w[k * 4096 + t];
    }
    if (tid < 64) sb[tid] = b[k * 64 + tid];
    __syncthreads();

    int nl = tid & 63, q = tid >> 6;
    float acc[16];
#pragma unroll
    for (int d = 0; d < 16; d++) acc[d] = 0.f;

#pragma unroll 4
    for (int e = 0; e < 64; e++) {
        float a = semb[nl * 65 + e];
#pragma unroll
        for (int jj = 0; jj < 4; jj++) {
            float4 wv = *(const float4*)&sw[e * 64 + q * 16 + jj * 4];
            acc[jj * 4 + 0] += a * wv.x;
            acc[jj * 4 + 1] += a * wv.y;
            acc[jj * 4 + 2] += a * wv.z;
            acc[jj * 4 + 3] += a * wv.w;
        }
    }

    size_t rowoff = (size_t)(k * NSUB + tile * 64 + nl) * 64;
    float* orow = vout + rowoff;
    __nv_bfloat16* orowb = voutb + rowoff;
#pragma unroll
    for (int dd = 0; dd < 16; dd++) {
        int d = q * 16 + dd;
        float v = acc[dd] + sb[d];
        orow[d]  = v;
        orowb[d] = __float2bfloat16(v);
    }
}

// ---------------------------------------------------------------------------
// HMMA plumbing. 512 threads: warp w = (rowband rb = w&7) x (colhalf ch = w>>3).
// Warp computes 16 rows x 32 cols per 64-col chunk.
// ---------------------------------------------------------------------------
#define OFF_A  0
#define OFF_B  18432
#define SM_AB  36864            // A + 2 B buffers

// one chunk's 16 accumulators (4 n-tiles x 4 regs) for this warp's 32-col half
#define MMA_CHUNK4(acc, af, bbuf, ch, lane)                                     \
    do {                                                                        \
        uint32_t baddr0 = (bbuf) + ((ch) * 32 + ((lane) & 7)) * 144             \
                          + (((lane) >> 3) & 1) * 16;                           \
        _Pragma("unroll")                                                       \
        for (int nt = 0; nt < 4; nt++) {                                        \
            uint32_t ba = baddr0 + nt * 8 * 144;                                \
            _Pragma("unroll")                                                   \
            for (int ks = 0; ks < 4; ks++) {                                    \
                uint32_t b0, b1;                                                \
                asm volatile("ldmatrix.sync.aligned.m8n8.x2.shared.b16 {%0,%1}, [%2];" \
                             : "=r"(b0), "=r"(b1) : "r"(ba + ks * 32));         \
                asm volatile("mma.sync.aligned.m16n8k16.row.col.f32.bf16.bf16.f32 " \
                             "{%0,%1,%2,%3}, {%4,%5,%6,%7}, {%8,%9}, {%0,%1,%2,%3};" \
                             : "+f"(acc[nt][0]), "+f"(acc[nt][1]),              \
                               "+f"(acc[nt][2]), "+f"(acc[nt][3])               \
                             : "r"(af[ks][0]), "r"(af[ks][1]),                  \
                               "r"(af[ks][2]), "r"(af[ks][3]), "r"(b0), "r"(b1)); \
            }                                                                   \
        }                                                                       \
    } while (0)

__device__ __forceinline__ void load_A_and_B0(char* smem, int tid, int k, int nbase) {
    const int4* asrc = (const int4*)&g_v1b[k][nbase][0];
    for (int f = tid; f < 1024; f += 512) {
        int r = f >> 3, q = f & 7;
        *(int4*)(smem + OFF_A + r * 144 + q * 16) = asrc[f];
    }
    const int4* bsrc = (const int4*)&g_v2b[k][0][0];
    for (int f = tid; f < 512; f += 512) {
        int r = f >> 3, q = f & 7;
        *(int4*)(smem + OFF_B + r * 144 + q * 16) = bsrc[f];
    }
}

__device__ __forceinline__ void preload_af(uint32_t af[4][4], uint32_t sbase, int rb, int lane) {
    uint32_t abase = sbase + OFF_A + (rb * 16 + (lane & 15)) * 144 + (lane >> 4) * 16;
#pragma unroll
    for (int ks = 0; ks < 4; ks++) {
        asm volatile("ldmatrix.sync.aligned.m8n8.x4.shared.b16 {%0,%1,%2,%3}, [%4];"
                     : "=r"(af[ks][0]), "=r"(af[ks][1]), "=r"(af[ks][2]), "=r"(af[ks][3])
                     : "r"(abase + ks * 32));
    }
}

__device__ __forceinline__ void prefetch_B(char* smem, int tid, int k, int cc1) {
    const int4* src = (const int4*)&g_v2b[k][cc1 * 64][0];
    char* dst = smem + OFF_B + (cc1 & 1) * 9216;
    for (int f = tid; f < 512; f += 512) {
        int r = f >> 3, q = f & 7;
        *(int4*)(dst + r * 144 + q * 16) = src[f];
    }
}

// ---------------------------------------------------------------------------
// Pass 1: HMMA + per-row 32-col sub-chunk maxima. grid (half:2, rowtile:64).
// ---------------------------------------------------------------------------
__global__ void __launch_bounds__(512, 1) score1_kernel() {
    extern __shared__ char smem[];
    uint32_t sbase = smem_u32(smem);
    int tid = threadIdx.x, wid = tid >> 5, lane = tid & 31;
    int rb = wid & 7, ch = wid >> 3;
    int half = blockIdx.x, rt = blockIdx.y;
    int k = (rt >> 5) * 2 + half;
    int nbase = (rt & 31) * 128;
    int rowg0 = rt * 128;

    load_A_and_B0(smem, tid, k, nbase);
    __syncthreads();

    uint32_t af[4][4];
    preload_af(af, sbase, rb, lane);

    int drow = rb * 16 + (lane >> 2);

    for (int cc = 0; cc < 64; cc++) {
        if (cc + 1 < 64) prefetch_B(smem, tid, k, cc + 1);

        uint32_t bbuf = sbase + OFF_B + (cc & 1) * 9216;
        float acc[4][4];
#pragma unroll
        for (int nt = 0; nt < 4; nt++)
#pragma unroll
            for (int s = 0; s < 4; s++) acc[nt][s] = 0.f;
        MMA_CHUNK4(acc, af, bbuf, ch, lane);

        float mlo = acc[0][0], mhi = acc[0][2];
#pragma unroll
        for (int nt = 0; nt < 4; nt++) {
            mlo = fmaxf(mlo, fmaxf(acc[nt][0], acc[nt][1]));
            mhi = fmaxf(mhi, fmaxf(acc[nt][2], acc[nt][3]));
        }
        mlo = fmaxf(mlo, __shfl_xor_sync(FULLM, mlo, 1));
        mlo = fmaxf(mlo, __shfl_xor_sync(FULLM, mlo, 2));
        mhi = fmaxf(mhi, __shfl_xor_sync(FULLM, mhi, 1));
        mhi = fmaxf(mhi, __shfl_xor_sync(FULLM, mhi, 2));
        if ((lane & 3) == 0) {
            g_cm[rowg0 + drow][half * 128 + cc * 2 + ch]     = mlo;
            g_cm[rowg0 + drow + 8][half * 128 + cc * 2 + ch] = mhi;
        }
        __syncthreads();
    }
}

// ---------------------------------------------------------------------------
// Threshold: T[row] = (20th largest of 256 sub-chunk maxima) - DELTA.
// warp/row, value-only fmax rounds (duplicate removal is conservative-safe).
// ---------------------------------------------------------------------------
__global__ void thr_kernel() {
    int w = threadIdx.x >> 5, lane = threadIdx.x & 31;
    int row = blockIdx.x * 8 + w;

    float a[8];
#pragma unroll
    for (int s = 0; s < 8; s++) a[s] = g_cm[row][lane + 32 * s];

    float last = -1e30f;
#pragma unroll
    for (int kk = 0; kk < KTOP; kk++) {
        float bv = a[0];
#pragma unroll
        for (int s = 1; s < 8; s++) bv = fmaxf(bv, a[s]);
#pragma unroll
        for (int off = 16; off > 0; off >>= 1)
            bv = fmaxf(bv, __shfl_xor_sync(FULLM, bv, off));
#pragma unroll
        for (int s = 0; s < 8; s++) a[s] = (a[s] == bv) ? -1e30f : a[s];
        last = bv;
    }
    if (lane == 0) g_T[row] = last - DELTA;
}

// ---------------------------------------------------------------------------
// Pass 2: HMMA + filter-append values > T into per-row FIFOs.
// ---------------------------------------------------------------------------
#define OFF_FV 36864
#define OFF_FC 61440
#define OFF_CN 73728
#define SM2_TOTAL 74240

__global__ void __launch_bounds__(512, 1) score2_kernel() {
    extern __shared__ char smem[];
    uint32_t sbase = smem_u32(smem);
    int tid = threadIdx.x, wid = tid >> 5, lane = tid & 31;
    int rb = wid & 7, ch = wid >> 3;
    int half = blockIdx.x, rt = blockIdx.y;
    int k = (rt >> 5) * 2 + half;
    int nbase = (rt & 31) * 128;
    int rowg0 = rt * 128;

    float* fv = (float*)(smem + OFF_FV);
    unsigned short* fc = (unsigned short*)(smem + OFF_FC);
    int* cnt = (int*)(smem + OFF_CN);
    if (tid < 128) cnt[tid] = 0;

    load_A_and_B0(smem, tid, k, nbase);
    __syncthreads();

    uint32_t af[4][4];
    preload_af(af, sbase, rb, lane);

    int drow = rb * 16 + (lane >> 2);
    int dcol = (lane & 3) * 2;
    float Tlo = g_T[rowg0 + drow];
    float Thi = g_T[rowg0 + drow + 8];
    int cbase = half * 4096;

    for (int cc = 0; cc < 64; cc++) {
        if (cc + 1 < 64) prefetch_B(smem, tid, k, cc + 1);

        uint32_t bbuf = sbase + OFF_B + (cc & 1) * 9216;
        float acc[4][4];
#pragma unroll
        for (int nt = 0; nt < 4; nt++)
#pragma unroll
            for (int s = 0; s < 4; s++) acc[nt][s] = 0.f;
        MMA_CHUNK4(acc, af, bbuf, ch, lane);

#pragma unroll
        for (int nt = 0; nt < 4; nt++) {
            int colb = cc * 64 + ch * 32 + nt * 8 + dcol;
            if (acc[nt][0] > Tlo) {
                int p = atomicAdd(&cnt[drow], 1);
                if (p < CAND) { fv[drow * CAND + p] = acc[nt][0];
                                fc[drow * CAND + p] = (unsigned short)(cbase + colb); }
            }
            if (acc[nt][1] > Tlo) {
                int p = atomicAdd(&cnt[drow], 1);
                if (p < CAND) { fv[drow * CAND + p] = acc[nt][1];
                                fc[drow * CAND + p] = (unsigned short)(cbase + colb + 1); }
            }
            if (acc[nt][2] > Thi) {
                int p = atomicAdd(&cnt[drow + 8], 1);
                if (p < CAND) { fv[(drow + 8) * CAND + p] = acc[nt][2];
                                fc[(drow + 8) * CAND + p] = (unsigned short)(cbase + colb); }
            }
            if (acc[nt][3] > Thi) {
                int p = atomicAdd(&cnt[drow + 8], 1);
                if (p < CAND) { fv[(drow + 8) * CAND + p] = acc[nt][3];
                                fc[(drow + 8) * CAND + p] = (unsigned short)(cbase + colb + 1); }
            }
        }
        __syncthreads();
    }

    for (int t = tid; t < 128 * CAND; t += 512) {
        int r = t / CAND, i = t % CAND;
        int n = min(cnt[r], CAND);
        g_cval[rowg0 + r][half * CAND + i] = (i < n) ? fv[t] : -1e30f;
        g_ccol[rowg0 + r][half * CAND + i] = fc[t];
    }
}

// ---------------------------------------------------------------------------
// Merge (+fused output zeroing): block = 8 rows. Zero the 8 output rows,
// then warp/row: rescore <=96 candidates in exact fp32, top-20, scatter.
// ---------------------------------------------------------------------------
__global__ void merge_rescore_kernel(float* __restrict__ out) {
    __shared__ float sv1[8][2][64];
    int tid = threadIdx.x;
    int w = tid >> 5, lane = tid & 31;
    int row0 = blockIdx.x * 8;
    int row = row0 + w;
    int mod_i = row >> 12, rloc = row & 4095;

    // zero this block's 8 output rows (256MB total across grid)
    {
        float4* ob = (float4*)(out + (size_t)row0 * NROWS);
        for (int t = tid; t < 8 * NROWS / 4; t += 256)
            ob[t] = make_float4(0.f, 0.f, 0.f, 0.f);
    }

    for (int t = lane; t < 128; t += 32) {
        int h = t >> 6, d = t & 63;
        sv1[w][h][d] = g_v1[mod_i * 2 + h][rloc][d];
    }
    __syncthreads();

    float rv[3]; int gc[3];
#pragma unroll
    for (int s = 0; s < 3; s++) {
        int idx = lane * 3 + s;
        float bval = g_cval[row][idx];
        int   col  = (int)g_ccol[row][idx];
        gc[s] = col;
        if (bval > -1e29f) {
            int h = col >> 12, cl = col & 4095;
            const float4* v2c = (const float4*)&g_v2[mod_i * 2 + h][cl][0];
            const float4* v1c = (const float4*)&sv1[w][h][0];
            float acc = 0.f;
#pragma unroll
            for (int dd = 0; dd < 16; dd++) {
                float4 x = v1c[dd], y = v2c[dd];
                acc += x.x * y.x + x.y * y.y + x.z * y.z + x.w * y.w;
            }
            rv[s] = acc;
        } else {
            rv[s] = -1e30f;
        }
    }

#pragma unroll
    for (int kk = 0; kk < KTOP; kk++) {
        float bv = rv[0]; int bs = 0;
        if (rv[1] > bv) { bv = rv[1]; bs = 1; }
        if (rv[2] > bv) { bv = rv[2]; bs = 2; }
        int bc = gc[bs];
        int bi = lane * 4 + bs;
#pragma unroll
        for (int off = 16; off > 0; off >>= 1) {
            float ov = __shfl_xor_sync(FULLM, bv, off);
            int   oc = __shfl_xor_sync(FULLM, bc, off);
            int   oi = __shfl_xor_sync(FULLM, bi, off);
            if (ov > bv || (ov == bv && oi < bi)) { bv = ov; bc = oc; bi = oi; }
        }
        if (lane == (bi >> 2)) rv[bi & 3] = -1e30f;
        if (lane == kk) {
            float t = (bv > 0.f) ? tanhf(3.0f * bv) : 0.f;
            out[(size_t)row * NROWS + bc] = t;
        }
    }
}

// ---------------------------------------------------------------------------
extern "C" void kernel_launch(void* const* d_in, const int* in_sizes, int n_in,
                              void* d_out, int out_size) {
    const float* emb1 = (const float*)d_in[1];
    const float* emb2 = (const float*)d_in[2];
    const float* w1   = (const float*)d_in[3];
    const float* w2   = (const float*)d_in[4];
    const float* b1   = (const float*)d_in[5];
    const float* b2   = (const float*)d_in[6];
    float* out = (float*)d_out;

    cudaFuncSetAttribute(score1_kernel,
                         cudaFuncAttributeMaxDynamicSharedMemorySize, SM_AB);
    cudaFuncSetAttribute(score2_kernel,
                         cudaFuncAttributeMaxDynamicSharedMemorySize, SM2_TOTAL);

    compute_v_kernel<<<dim3(64, NMAT, 2), 256>>>(emb1, emb2, w1, w2, b1, b2);
    score1_kernel<<<dim3(2, 64), 512, SM_AB>>>();
    thr_kernel<<<NROWS / 8, 256>>>();
    score2_kernel<<<dim3(2, 64), 512, SM2_TOTAL>>>();
    merge_rescore_kernel<<<NROWS / 8, 256>>>(out);
}